// round 1
// baseline (speedup 1.0000x reference)
#include <cuda_runtime.h>

// Problem constants (fixed by setup_inputs)
#define BS   8
#define NA   128
#define NC   256
#define DD   64
#define HHH  64
#define ZZ   8
#define NT   3
#define NET  9
#define NETASK (BS*NC*3)   // 6144 edge tasks
#define NNODE  (BS*NA)     // 1024 nodes
#define OUT_LOGPI (BS*NC*ZZ*ZZ*ZZ)   // 1048576

// ---------------- device scratch (no allocations allowed) ----------------
__device__ __align__(16) float g_nf[NNODE*ZZ];        // node factors
__device__ __align__(16) float g_ef[NETASK*64];       // edge factors per task
__device__ int g_ecnt[NET];
__device__ int g_ebucket[NET*NETASK];
__device__ int g_ncnt[NT];
__device__ int g_nbucket[NT*NNODE];

static __device__ __forceinline__ int clampi(int v, int lo, int hi) {
    return v < lo ? lo : (v > hi ? hi : v);
}

// ---------------- kernel: zero bucket counters ----------------
__global__ void zero_counts_kernel() {
    int t = threadIdx.x;
    if (t < NET) g_ecnt[t] = 0;
    if (t < NT)  g_ncnt[t] = 0;
}

// ---------------- kernel: bin edge tasks by edge-type, nodes by node-type --
__global__ void bin_tasks_kernel(const int* __restrict__ types,
                                 const int* __restrict__ cni) {
    int t = blockIdx.x * blockDim.x + threadIdx.x;
    if (t < NETASK) {
        int b   = t / (NC*3);
        int rem = t - b*(NC*3);
        int c   = rem / 3;
        int p   = rem - 3*c;              // pair id: 0->(0,1) 1->(0,2) 2->(1,2)
        int a0  = (p == 2) ? 1 : 0;
        int a1  = (p == 0) ? 1 : 2;
        int i = clampi(cni[(b*NC + c)*3 + a0], 0, NA-1);
        int j = clampi(cni[(b*NC + c)*3 + a1], 0, NA-1);
        int ti = clampi(types[b*NA + i], 0, NT-1);
        int tj = clampi(types[b*NA + j], 0, NT-1);
        int et = tj*3 + ti;               // emask: pa==type[j], pb==type[i]
        int pos = atomicAdd(&g_ecnt[et], 1);
        g_ebucket[et*NETASK + pos] = t;
    } else {
        int nn = t - NETASK;
        if (nn < NNODE) {
            int ty = clampi(types[nn], 0, NT-1);
            int pos = atomicAdd(&g_ncnt[ty], 1);
            g_nbucket[ty*NNODE + pos] = nn;
        }
    }
}

// ---------------- shared 32x64 @ 64x64 layer helper ----------------
// sIn: [32][68] (padded), sW: [64][64], sb: bias[64]
// thread tile: tx in [0,16) -> 4 cols, ty in [0,16) -> rows ty, ty+16
__device__ __forceinline__ void layer64_acc(const float* __restrict__ sIn,
                                            const float* __restrict__ sW,
                                            const float* __restrict__ sb,
                                            int tx, int ty, float acc[8]) {
    float4 bv = *(const float4*)(sb + tx*4);
    acc[0]=bv.x; acc[1]=bv.y; acc[2]=bv.z; acc[3]=bv.w;
    acc[4]=bv.x; acc[5]=bv.y; acc[6]=bv.z; acc[7]=bv.w;
    const float* in0 = sIn + ty*68;
    const float* in1 = sIn + (ty+16)*68;
    #pragma unroll 16
    for (int d = 0; d < 64; d++) {
        float x0 = in0[d];
        float x1 = in1[d];
        float4 w = *(const float4*)(sW + d*64 + tx*4);
        acc[0] += x0*w.x; acc[1] += x0*w.y; acc[2] += x0*w.z; acc[3] += x0*w.w;
        acc[4] += x1*w.x; acc[5] += x1*w.y; acc[6] += x1*w.z; acc[7] += x1*w.w;
    }
}

__device__ __forceinline__ void store_relu(float* __restrict__ sOut,
                                           int tx, int ty, const float acc[8]) {
    float4 v0 = make_float4(fmaxf(acc[0],0.f), fmaxf(acc[1],0.f),
                            fmaxf(acc[2],0.f), fmaxf(acc[3],0.f));
    float4 v1 = make_float4(fmaxf(acc[4],0.f), fmaxf(acc[5],0.f),
                            fmaxf(acc[6],0.f), fmaxf(acc[7],0.f));
    *(float4*)(sOut + ty*68 + tx*4)      = v0;
    *(float4*)(sOut + (ty+16)*68 + tx*4) = v1;
}

// ---------------- kernel: edge MLPs, one type per CTA ----------------
// grid: NET * 192 CTAs (192 chunks of 32 tasks covers worst case 6144/type)
__global__ __launch_bounds__(256) void edge_mlp_kernel(
    const float* __restrict__ edge_enc, const int* __restrict__ cni,
    const float* __restrict__ eW0, const float* __restrict__ eb0,
    const float* __restrict__ eW1, const float* __restrict__ eb1,
    const float* __restrict__ eW2, const float* __restrict__ eb2)
{
    int g     = blockIdx.x / 192;
    int chunk = blockIdx.x % 192;
    int cnt   = g_ecnt[g];
    int base  = chunk * 32;
    if (base >= cnt) return;
    int ntask = min(32, cnt - base);

    __shared__ __align__(16) float sW[64*64];
    __shared__ __align__(16) float sb[64];
    __shared__ __align__(16) float sA[32*68];
    __shared__ __align__(16) float sB[32*68];
    __shared__ int s_tt[32];
    __shared__ int s_eoff[32];

    int tid = threadIdx.x;
    int tx = tid & 15, ty = tid >> 4;

    // decode tasks
    if (tid < ntask) {
        int tt = g_ebucket[g*NETASK + base + tid];
        s_tt[tid] = tt;
        int b   = tt / (NC*3);
        int rem = tt - b*(NC*3);
        int c   = rem / 3;
        int p   = rem - 3*c;
        int a0  = (p == 2) ? 1 : 0;
        int a1  = (p == 0) ? 1 : 2;
        int i = clampi(cni[(b*NC + c)*3 + a0], 0, NA-1);
        int j = clampi(cni[(b*NC + c)*3 + a1], 0, NA-1);
        s_eoff[tid] = ((b*NA + i)*NA + j) * DD;
    }
    // stage W0, b0
    {
        const float4* w = (const float4*)(eW0 + g*4096);
        float4* sw = (float4*)sW;
        #pragma unroll
        for (int k = 0; k < 4; k++) sw[tid + 256*k] = w[tid + 256*k];
        if (tid < 64) sb[tid] = eb0[g*64 + tid];
    }
    __syncthreads();
    // gather edge vectors (64 f32 each) into sA
    for (int k = tid; k < ntask*16; k += 256) {
        int s = k >> 4, q = k & 15;
        float4 v = *(const float4*)(edge_enc + s_eoff[s] + q*4);
        *(float4*)(sA + s*68 + q*4) = v;
    }
    __syncthreads();

    float acc[8];
    // layer 0: sA -> sB (relu)
    layer64_acc(sA, sW, sb, tx, ty, acc);
    __syncthreads();                    // done reading sW before reload
    store_relu(sB, tx, ty, acc);
    // stage W1, b1
    {
        const float4* w = (const float4*)(eW1 + g*4096);
        float4* sw = (float4*)sW;
        #pragma unroll
        for (int k = 0; k < 4; k++) sw[tid + 256*k] = w[tid + 256*k];
        if (tid < 64) sb[tid] = eb1[g*64 + tid];
    }
    __syncthreads();
    // layer 1: sB -> sA (relu)
    layer64_acc(sB, sW, sb, tx, ty, acc);
    __syncthreads();
    store_relu(sA, tx, ty, acc);
    // stage W2, b2
    {
        const float4* w = (const float4*)(eW2 + g*4096);
        float4* sw = (float4*)sW;
        #pragma unroll
        for (int k = 0; k < 4; k++) sw[tid + 256*k] = w[tid + 256*k];
        if (tid < 64) sb[tid] = eb2[g*64 + tid];
    }
    __syncthreads();
    // layer 2: sA -> global (no relu)
    layer64_acc(sA, sW, sb, tx, ty, acc);
    if (ty < ntask) {
        float* o = g_ef + (size_t)s_tt[ty]*64 + tx*4;
        *(float4*)o = make_float4(acc[0], acc[1], acc[2], acc[3]);
    }
    if (ty + 16 < ntask) {
        float* o = g_ef + (size_t)s_tt[ty+16]*64 + tx*4;
        *(float4*)o = make_float4(acc[4], acc[5], acc[6], acc[7]);
    }
}

// ---------------- kernel: node MLPs, one type per CTA ----------------
// grid: NT * 32
__global__ __launch_bounds__(256) void node_mlp_kernel(
    const float* __restrict__ node_enc,
    const float* __restrict__ nW0, const float* __restrict__ nb0,
    const float* __restrict__ nW1, const float* __restrict__ nb1,
    const float* __restrict__ nW2, const float* __restrict__ nb2)
{
    int g     = blockIdx.x / 32;
    int chunk = blockIdx.x % 32;
    int cnt   = g_ncnt[g];
    int base  = chunk * 32;
    if (base >= cnt) return;
    int ntask = min(32, cnt - base);

    __shared__ __align__(16) float sW[64*64];
    __shared__ __align__(16) float sb[64];
    __shared__ __align__(16) float sA[32*68];
    __shared__ __align__(16) float sB[32*68];
    __shared__ int s_nn[32];

    int tid = threadIdx.x;
    int tx = tid & 15, ty = tid >> 4;

    if (tid < ntask) s_nn[tid] = g_nbucket[g*NNODE + base + tid];
    {
        const float4* w = (const float4*)(nW0 + g*4096);
        float4* sw = (float4*)sW;
        #pragma unroll
        for (int k = 0; k < 4; k++) sw[tid + 256*k] = w[tid + 256*k];
        if (tid < 64) sb[tid] = nb0[g*64 + tid];
    }
    __syncthreads();
    for (int k = tid; k < ntask*16; k += 256) {
        int s = k >> 4, q = k & 15;
        float4 v = *(const float4*)(node_enc + (size_t)s_nn[s]*64 + q*4);
        *(float4*)(sA + s*68 + q*4) = v;
    }
    __syncthreads();

    float acc[8];
    layer64_acc(sA, sW, sb, tx, ty, acc);
    __syncthreads();
    store_relu(sB, tx, ty, acc);
    {
        const float4* w = (const float4*)(nW1 + g*4096);
        float4* sw = (float4*)sW;
        #pragma unroll
        for (int k = 0; k < 4; k++) sw[tid + 256*k] = w[tid + 256*k];
        if (tid < 64) sb[tid] = nb1[g*64 + tid];
    }
    __syncthreads();
    layer64_acc(sB, sW, sb, tx, ty, acc);
    __syncthreads();
    store_relu(sA, tx, ty, acc);
    // final layer: 64 -> 8
    {
        const float4* w = (const float4*)(nW2 + g*512);
        float4* sw = (float4*)sW;
        if (tid < 128) sw[tid] = w[tid];          // 512 floats
        if (tid < 8) sb[tid] = nb2[g*8 + tid];
    }
    __syncthreads();
    {
        int row = tid >> 3, col = tid & 7;        // 32 rows x 8 cols
        float a = sb[col];
        const float* in = sA + row*68;
        #pragma unroll 16
        for (int d = 0; d < 64; d++) a += in[d] * sW[d*8 + col];
        if (row < ntask) g_nf[(size_t)s_nn[row]*8 + col] = a;
    }
}

// ---------------- kernel: assemble logpi ----------------
// grid: BS*NC blocks, 64 threads
__global__ __launch_bounds__(64) void assemble_kernel(
    const int* __restrict__ types, const int* __restrict__ cni,
    float* __restrict__ out)
{
    int cq = blockIdx.x;        // b*NC + c
    int tid = threadIdx.x;      // 0..63
    __shared__ float nf[3][8];
    __shared__ float e01[64], e02[64], e12[64];

    size_t tbase = (size_t)cq*3*64;
    e01[tid] = g_ef[tbase + 0*64 + tid];
    e02[tid] = g_ef[tbase + 1*64 + tid];
    e12[tid] = g_ef[tbase + 2*64 + tid];
    if (tid < 24) {
        int k = tid >> 3, zz = tid & 7;
        int b = cq / NC;
        int node = clampi(cni[cq*3 + k], 0, NA-1);
        nf[k][zz] = g_nf[((size_t)b*NA + node)*8 + zz];
    }
    __syncthreads();

    int z0 = tid >> 3, z1 = tid & 7;
    float bse = nf[0][z0] + nf[1][z1] + e01[z0*8 + z1];
    float r[8];
    #pragma unroll
    for (int z2 = 0; z2 < 8; z2++)
        r[z2] = bse + nf[2][z2] + e02[z0*8 + z2] + e12[z1*8 + z2];
    float* op = out + (size_t)cq*512 + tid*8;
    *(float4*)op       = make_float4(r[0], r[1], r[2], r[3]);
    *(float4*)(op + 4) = make_float4(r[4], r[5], r[6], r[7]);
}

// ---------------- kernel: meshgrid z tail (if the harness flattens the tuple)
__global__ void write_z_kernel(float* __restrict__ out) {
    int m = threadIdx.x;           // 512
    int i = m >> 6, j = (m >> 3) & 7, k = m & 7;
    float* p = out + OUT_LOGPI + (size_t)m*3;
    p[0] = (float)i; p[1] = (float)j; p[2] = (float)k;
}

// ---------------- launch ----------------
extern "C" void kernel_launch(void* const* d_in, const int* in_sizes, int n_in,
                              void* d_out, int out_size) {
    const int*   types    = (const int*)d_in[0];
    const float* node_enc = (const float*)d_in[1];
    const float* edge_enc = (const float*)d_in[2];
    const int*   cni      = (const int*)d_in[4];   // clique_node_index
    const float* nW0 = (const float*)d_in[6];
    const float* nb0 = (const float*)d_in[7];
    const float* nW1 = (const float*)d_in[8];
    const float* nb1 = (const float*)d_in[9];
    const float* nW2 = (const float*)d_in[10];
    const float* nb2 = (const float*)d_in[11];
    const float* eW0 = (const float*)d_in[12];
    const float* eb0 = (const float*)d_in[13];
    const float* eW1 = (const float*)d_in[14];
    const float* eb1 = (const float*)d_in[15];
    const float* eW2 = (const float*)d_in[16];
    const float* eb2 = (const float*)d_in[17];
    float* out = (float*)d_out;

    zero_counts_kernel<<<1, 32>>>();
    bin_tasks_kernel<<<(NETASK + NNODE + 255) / 256, 256>>>(types, cni);
    node_mlp_kernel<<<NT * 32, 256>>>(node_enc, nW0, nb0, nW1, nb1, nW2, nb2);
    edge_mlp_kernel<<<NET * 192, 256>>>(edge_enc, cni,
                                        eW0, eb0, eW1, eb1, eW2, eb2);
    assemble_kernel<<<BS * NC, 64>>>(types, cni, out);
    if (out_size >= OUT_LOGPI + 512*3)
        write_z_kernel<<<1, 512>>>(out);
}

// round 2
// speedup vs baseline: 1.8567x; 1.8567x over previous
#include <cuda_runtime.h>

// Problem constants (fixed by setup_inputs)
#define BS   8
#define NA   128
#define NC   256
#define ZZ   8
#define NT   3
#define NET  9
#define NETASK (BS*NC*3)   // 6144 edge tasks
#define NNODE  (BS*NA)     // 1024 node tasks
#define OUT_LOGPI (BS*NC*ZZ*ZZ*ZZ)   // 1048576

typedef unsigned long long u64;

// ---------------- device scratch (no allocations allowed) ----------------
__device__ __align__(16) float g_nf[NNODE*ZZ];
__device__ __align__(16) float g_ef[NETASK*64];
__device__ int g_ecnt[NET];          // zero at load; re-zeroed by assemble
__device__ int g_ncnt[NT];
__device__ int g_ebucket[NET*NETASK];
__device__ int g_nbucket[NT*NNODE];

static __device__ __forceinline__ int clampi(int v, int lo, int hi) {
    return v < lo ? lo : (v > hi ? hi : v);
}

// ---------------- packed f32x2 helpers (FFMA2: 2 FMAs per instruction) ----
static __device__ __forceinline__ u64 pack2(float a, float b) {
    u64 r; asm("mov.b64 %0, {%1, %2};" : "=l"(r) : "f"(a), "f"(b)); return r;
}
static __device__ __forceinline__ void unpack2(u64 v, float& a, float& b) {
    asm("mov.b64 {%0, %1}, %2;" : "=f"(a), "=f"(b) : "l"(v));
}
static __device__ __forceinline__ void ffma2(u64& d, u64 a, u64 b) {
    asm("fma.rn.f32x2 %0, %1, %2, %0;" : "+l"(d) : "l"(a), "l"(b));
}

// ---------------- kernel: bin edge tasks by edge-type, nodes by node-type --
__global__ void bin_tasks_kernel(const int* __restrict__ types,
                                 const int* __restrict__ cni) {
    int t = blockIdx.x * blockDim.x + threadIdx.x;
    if (t < NETASK) {
        int b   = t / (NC*3);
        int rem = t - b*(NC*3);
        int c   = rem / 3;
        int p   = rem - 3*c;              // pair: 0->(0,1) 1->(0,2) 2->(1,2)
        int a0  = (p == 2) ? 1 : 0;
        int a1  = (p == 0) ? 1 : 2;
        int i = clampi(cni[(b*NC + c)*3 + a0], 0, NA-1);
        int j = clampi(cni[(b*NC + c)*3 + a1], 0, NA-1);
        int ti = clampi(types[b*NA + i], 0, NT-1);
        int tj = clampi(types[b*NA + j], 0, NT-1);
        int et = tj*3 + ti;               // emask: pa==type[j], pb==type[i]
        int pos = atomicAdd(&g_ecnt[et], 1);
        g_ebucket[et*NETASK + pos] = t;
    } else {
        int nn = t - NETASK;
        if (nn < NNODE) {
            int ty = clampi(types[nn], 0, NT-1);
            int pos = atomicAdd(&g_ncnt[ty], 1);
            g_nbucket[ty*NNODE + pos] = nn;
        }
    }
}

// ---------------- 32x64 @ 64x64 layer via f32x2 ----------------
// sIn: [32][68] padded rows, sW: [64][64], sb: bias[64]
// thread (tx in [0,16), ty in [0,16)): rows {ty, ty+16}, cols [4tx, 4tx+4)
// acc[0]=(r0,c0|c1) acc[1]=(r0,c2|c3) acc[2]=(r1,c0|c1) acc[3]=(r1,c2|c3)
static __device__ __forceinline__ void layer64(const float* __restrict__ sIn,
                                               const float* __restrict__ sW,
                                               const float* __restrict__ sb,
                                               int tx, int ty, u64 acc[4]) {
    ulonglong2 bv = *(const ulonglong2*)(sb + tx*4);
    acc[0] = bv.x; acc[1] = bv.y; acc[2] = bv.x; acc[3] = bv.y;
    const float* in0 = sIn + ty*68;
    const float* in1 = sIn + (ty+16)*68;
    #pragma unroll
    for (int d0 = 0; d0 < 64; d0 += 4) {
        float4 x0 = *(const float4*)(in0 + d0);
        float4 x1 = *(const float4*)(in1 + d0);
        {
            ulonglong2 w = *(const ulonglong2*)(sW + (d0+0)*64 + tx*4);
            u64 a0 = pack2(x0.x, x0.x), a1 = pack2(x1.x, x1.x);
            ffma2(acc[0], a0, w.x); ffma2(acc[1], a0, w.y);
            ffma2(acc[2], a1, w.x); ffma2(acc[3], a1, w.y);
        }
        {
            ulonglong2 w = *(const ulonglong2*)(sW + (d0+1)*64 + tx*4);
            u64 a0 = pack2(x0.y, x0.y), a1 = pack2(x1.y, x1.y);
            ffma2(acc[0], a0, w.x); ffma2(acc[1], a0, w.y);
            ffma2(acc[2], a1, w.x); ffma2(acc[3], a1, w.y);
        }
        {
            ulonglong2 w = *(const ulonglong2*)(sW + (d0+2)*64 + tx*4);
            u64 a0 = pack2(x0.z, x0.z), a1 = pack2(x1.z, x1.z);
            ffma2(acc[0], a0, w.x); ffma2(acc[1], a0, w.y);
            ffma2(acc[2], a1, w.x); ffma2(acc[3], a1, w.y);
        }
        {
            ulonglong2 w = *(const ulonglong2*)(sW + (d0+3)*64 + tx*4);
            u64 a0 = pack2(x0.w, x0.w), a1 = pack2(x1.w, x1.w);
            ffma2(acc[0], a0, w.x); ffma2(acc[1], a0, w.y);
            ffma2(acc[2], a1, w.x); ffma2(acc[3], a1, w.y);
        }
    }
}

static __device__ __forceinline__ void store_relu(float* __restrict__ sOut,
                                                  int tx, int ty, const u64 acc[4]) {
    float r0, r1, r2, r3;
    unpack2(acc[0], r0, r1); unpack2(acc[1], r2, r3);
    *(float4*)(sOut + ty*68 + tx*4) =
        make_float4(fmaxf(r0,0.f), fmaxf(r1,0.f), fmaxf(r2,0.f), fmaxf(r3,0.f));
    unpack2(acc[2], r0, r1); unpack2(acc[3], r2, r3);
    *(float4*)(sOut + (ty+16)*68 + tx*4) =
        make_float4(fmaxf(r0,0.f), fmaxf(r1,0.f), fmaxf(r2,0.f), fmaxf(r3,0.f));
}

// ---------------- combined node+edge MLP kernel ----------------
// grid 240 CTAs; CTA maps itself to (edge type, chunk) or (node type, chunk)
// via prefix scan of bucket counts. Each chunk = up to 32 tasks.
__global__ __launch_bounds__(256) void mlp_kernel(
    const float* __restrict__ node_enc, const float* __restrict__ edge_enc,
    const int* __restrict__ cni,
    const float* __restrict__ nW0, const float* __restrict__ nb0,
    const float* __restrict__ nW1, const float* __restrict__ nb1,
    const float* __restrict__ nW2, const float* __restrict__ nb2,
    const float* __restrict__ eW0, const float* __restrict__ eb0,
    const float* __restrict__ eW1, const float* __restrict__ eb1,
    const float* __restrict__ eW2, const float* __restrict__ eb2)
{
    // ---- role mapping (uniform across threads) ----
    int bid = blockIdx.x;
    int g = -1, chunk = 0, acc = 0, cnt = 0;
    bool isEdge = true;
    #pragma unroll
    for (int t = 0; t < NET; t++) {
        int n = g_ecnt[t];
        int c = (n + 31) >> 5;
        if (g < 0 && bid < acc + c) { g = t; chunk = bid - acc; cnt = n; }
        acc += c;
    }
    if (g < 0) {
        isEdge = false;
        int nb = bid - acc; acc = 0;
        #pragma unroll
        for (int t = 0; t < NT; t++) {
            int n = g_ncnt[t];
            int c = (n + 31) >> 5;
            if (g < 0 && nb < acc + c) { g = t; chunk = nb - acc; cnt = n; }
            acc += c;
        }
        if (g < 0) return;
    }
    int base  = chunk * 32;
    int ntask = min(32, cnt - base);

    __shared__ __align__(16) float sW[64*64];
    __shared__ __align__(16) float sb0[64], sb1[64], sb2[64];
    __shared__ __align__(16) float sA[32*68];
    __shared__ __align__(16) float sB[32*68];
    __shared__ int s_idx[32];
    __shared__ int s_off[32];

    int tid = threadIdx.x;
    int tx = tid & 15, ty = tid >> 4;

    const float *W0, *W1, *b0, *b1, *inBase;
    if (isEdge) {
        W0 = eW0 + g*4096; W1 = eW1 + g*4096;
        b0 = eb0 + g*64;   b1 = eb1 + g*64;
        inBase = edge_enc;
        if (tid < ntask) {
            int tt = g_ebucket[g*NETASK + base + tid];
            s_idx[tid] = tt;
            int b   = tt / (NC*3);
            int rem = tt - b*(NC*3);
            int c   = rem / 3;
            int p   = rem - 3*c;
            int a0  = (p == 2) ? 1 : 0;
            int a1  = (p == 0) ? 1 : 2;
            int i = clampi(cni[(b*NC + c)*3 + a0], 0, NA-1);
            int j = clampi(cni[(b*NC + c)*3 + a1], 0, NA-1);
            s_off[tid] = ((b*NA + i)*NA + j) * 64;
        }
    } else {
        W0 = nW0 + g*4096; W1 = nW1 + g*4096;
        b0 = nb0 + g*64;   b1 = nb1 + g*64;
        inBase = node_enc;
        if (tid < ntask) {
            int nn = g_nbucket[g*NNODE + base + tid];
            s_idx[tid] = nn;
            s_off[tid] = nn * 64;
        }
    }

    // stage W0 + biases b0,b1
    {
        const float4* w = (const float4*)W0;
        float4* sw = (float4*)sW;
        #pragma unroll
        for (int k = 0; k < 4; k++) sw[tid + 256*k] = w[tid + 256*k];
        if (tid < 64) { sb0[tid] = b0[tid]; sb1[tid] = b1[tid]; }
    }
    __syncthreads();

    // gather input rows (uses s_off), prefetch W1 into registers meanwhile
    float4 pw[4];
    {
        const float4* w = (const float4*)W1;
        #pragma unroll
        for (int k = 0; k < 4; k++) pw[k] = w[tid + 256*k];
    }
    for (int k = tid; k < ntask*16; k += 256) {
        int s = k >> 4, q = k & 15;
        float4 v = *(const float4*)(inBase + (size_t)s_off[s] + q*4);
        *(float4*)(sA + s*68 + q*4) = v;
    }
    __syncthreads();

    u64 a4[4];
    // ---- layer 0: sA -> sB (relu) ----
    layer64(sA, sW, sb0, tx, ty, a4);
    __syncthreads();                    // all reads of sW(W0) done
    store_relu(sB, tx, ty, a4);
    {   // W1 regs -> smem
        float4* sw = (float4*)sW;
        #pragma unroll
        for (int k = 0; k < 4; k++) sw[tid + 256*k] = pw[k];
    }
    // prefetch layer-2 weights
    if (isEdge) {
        const float4* w = (const float4*)(eW2 + g*4096);
        #pragma unroll
        for (int k = 0; k < 4; k++) pw[k] = w[tid + 256*k];
        if (tid < 64) sb2[tid] = eb2[g*64 + tid];
    } else {
        if (tid < 128) pw[0] = ((const float4*)(nW2 + g*512))[tid];
        if (tid < 8)   sb2[tid] = nb2[g*8 + tid];
    }
    __syncthreads();

    // ---- layer 1: sB -> sA (relu) ----
    layer64(sB, sW, sb1, tx, ty, a4);
    __syncthreads();
    store_relu(sA, tx, ty, a4);
    {   // W2 regs -> smem
        float4* sw = (float4*)sW;
        if (isEdge) {
            #pragma unroll
            for (int k = 0; k < 4; k++) sw[tid + 256*k] = pw[k];
        } else {
            if (tid < 128) sw[tid] = pw[0];
        }
    }
    __syncthreads();

    // ---- layer 2 ----
    if (isEdge) {
        layer64(sA, sW, sb2, tx, ty, a4);     // no relu
        float r0, r1, r2, r3;
        if (ty < ntask) {
            unpack2(a4[0], r0, r1); unpack2(a4[1], r2, r3);
            *(float4*)(g_ef + (size_t)s_idx[ty]*64 + tx*4) = make_float4(r0, r1, r2, r3);
        }
        if (ty + 16 < ntask) {
            unpack2(a4[2], r0, r1); unpack2(a4[3], r2, r3);
            *(float4*)(g_ef + (size_t)s_idx[ty+16]*64 + tx*4) = make_float4(r0, r1, r2, r3);
        }
    } else {
        // 64 -> 8, one output per thread (32 rows x 8 cols)
        int row = tid >> 3, col = tid & 7;
        float a = sb2[col];
        const float* in = sA + row*68;
        #pragma unroll 16
        for (int d = 0; d < 64; d++) a += in[d] * sW[d*8 + col];
        if (row < ntask) g_nf[(size_t)s_idx[row]*8 + col] = a;
    }
}

// ---------------- kernel: assemble logpi (+ z tail, + counter re-zero) ----
// grid: BS*NC/4 blocks x 256 threads; 4 cliques per block
__global__ __launch_bounds__(256) void assemble_kernel(
    const int* __restrict__ cni, float* __restrict__ out, int writeZ)
{
    int tid = threadIdx.x;
    int sub = tid >> 6;                  // clique within block
    int t   = tid & 63;
    int cq  = blockIdx.x * 4 + sub;      // b*NC + c

    __shared__ float e[4][192];
    __shared__ float nf[4][3][8];

    size_t tbase = (size_t)cq * 192;
    e[sub][t]       = g_ef[tbase + t];
    e[sub][t + 64]  = g_ef[tbase + t + 64];
    e[sub][t + 128] = g_ef[tbase + t + 128];
    if (t < 24) {
        int k = t >> 3, zz = t & 7;
        int b = cq / NC;
        int node = clampi(cni[cq*3 + k], 0, NA-1);
        nf[sub][k][zz] = g_nf[((size_t)b*NA + node)*8 + zz];
    }

    if (blockIdx.x == 0) {               // housekeeping for next replay + z
        if (tid < NET) g_ecnt[tid] = 0;
        if (tid < NT)  g_ncnt[tid] = 0;
        if (writeZ) {
            for (int m = tid; m < 512; m += 256) {
                int i = m >> 6, j = (m >> 3) & 7, k = m & 7;
                float* p = out + OUT_LOGPI + (size_t)m*3;
                p[0] = (float)i; p[1] = (float)j; p[2] = (float)k;
            }
        }
    }
    __syncthreads();

    int z0 = t >> 3, z1 = t & 7;
    float bse = nf[sub][0][z0] + nf[sub][1][z1] + e[sub][z0*8 + z1];
    float r[8];
    #pragma unroll
    for (int z2 = 0; z2 < 8; z2++)
        r[z2] = bse + nf[sub][2][z2] + e[sub][64 + z0*8 + z2] + e[sub][128 + z1*8 + z2];
    float* op = out + (size_t)cq*512 + t*8;
    *(float4*)op       = make_float4(r[0], r[1], r[2], r[3]);
    *(float4*)(op + 4) = make_float4(r[4], r[5], r[6], r[7]);
}

// ---------------- launch ----------------
extern "C" void kernel_launch(void* const* d_in, const int* in_sizes, int n_in,
                              void* d_out, int out_size) {
    const int*   types    = (const int*)d_in[0];
    const float* node_enc = (const float*)d_in[1];
    const float* edge_enc = (const float*)d_in[2];
    const int*   cni      = (const int*)d_in[4];
    const float* nW0 = (const float*)d_in[6];
    const float* nb0 = (const float*)d_in[7];
    const float* nW1 = (const float*)d_in[8];
    const float* nb1 = (const float*)d_in[9];
    const float* nW2 = (const float*)d_in[10];
    const float* nb2 = (const float*)d_in[11];
    const float* eW0 = (const float*)d_in[12];
    const float* eb0 = (const float*)d_in[13];
    const float* eW1 = (const float*)d_in[14];
    const float* eb1 = (const float*)d_in[15];
    const float* eW2 = (const float*)d_in[16];
    const float* eb2 = (const float*)d_in[17];
    float* out = (float*)d_out;

    int writeZ = (out_size >= OUT_LOGPI + 512*3) ? 1 : 0;

    bin_tasks_kernel<<<(NETASK + NNODE + 255) / 256, 256>>>(types, cni);
    mlp_kernel<<<240, 256>>>(node_enc, edge_enc, cni,
                             nW0, nb0, nW1, nb1, nW2, nb2,
                             eW0, eb0, eW1, eb1, eW2, eb2);
    assemble_kernel<<<BS * NC / 4, 256>>>(cni, out, writeZ);
}

// round 3
// speedup vs baseline: 1.8595x; 1.0015x over previous
#include <cuda_runtime.h>

// Problem constants (fixed by setup_inputs)
#define BS   8
#define NA   128
#define NC   256
#define ZZ   8
#define NT   3
#define NET  9
#define NETASK (BS*NC*3)   // 6144 edge tasks
#define NNODE  (BS*NA)     // 1024 node tasks
#define OUT_LOGPI (BS*NC*ZZ*ZZ*ZZ)   // 1048576

typedef unsigned long long u64;

// ---------------- device scratch (no allocations allowed) ----------------
__device__ __align__(16) float g_nf[NNODE*ZZ];
__device__ __align__(16) float g_ef[NETASK*64];
__device__ int g_ecnt[NET];          // zero at load; re-zeroed by assemble
__device__ int g_ncnt[NT];
__device__ int g_ebucket[NET*NETASK];
__device__ int g_nbucket[NT*NNODE];

static __device__ __forceinline__ int clampi(int v, int lo, int hi) {
    return v < lo ? lo : (v > hi ? hi : v);
}

// ---------------- packed f32x2 helpers (FFMA2: 2 FMAs per instruction) ----
static __device__ __forceinline__ u64 pack2(float a, float b) {
    u64 r; asm("mov.b64 %0, {%1, %2};" : "=l"(r) : "f"(a), "f"(b)); return r;
}
static __device__ __forceinline__ void unpack2(u64 v, float& a, float& b) {
    asm("mov.b64 {%0, %1}, %2;" : "=f"(a), "=f"(b) : "l"(v));
}
static __device__ __forceinline__ void ffma2(u64& d, u64 a, u64 b) {
    asm("fma.rn.f32x2 %0, %1, %2, %0;" : "+l"(d) : "l"(a), "l"(b));
}

// ---------------- kernel: bin tasks, CTA-aggregated atomics ----------------
// grid: exactly (NETASK+NNODE)/256 = 28 CTAs.
// buckets: 0..8 = edge types, 9..11 = node types.
__global__ __launch_bounds__(256) void bin_tasks_kernel(
    const int* __restrict__ types, const int* __restrict__ cni)
{
    __shared__ int h[12];
    __shared__ int basev[12];
    int tid = threadIdx.x;
    int t = blockIdx.x * 256 + tid;
    if (tid < 12) h[tid] = 0;
    __syncthreads();

    int bk = -1, val = 0, pos = 0;
    if (t < NETASK) {
        int b   = t / (NC*3);
        int rem = t - b*(NC*3);
        int c   = rem / 3;
        int p   = rem - 3*c;              // pair: 0->(0,1) 1->(0,2) 2->(1,2)
        int a0  = (p == 2) ? 1 : 0;
        int a1  = (p == 0) ? 1 : 2;
        int i = clampi(cni[(b*NC + c)*3 + a0], 0, NA-1);
        int j = clampi(cni[(b*NC + c)*3 + a1], 0, NA-1);
        int ti = clampi(types[b*NA + i], 0, NT-1);
        int tj = clampi(types[b*NA + j], 0, NT-1);
        bk = tj*3 + ti;                   // emask: pa==type[j], pb==type[i]
        val = t;
    } else if (t < NETASK + NNODE) {
        int nn = t - NETASK;
        bk = 9 + clampi(types[nn], 0, NT-1);
        val = nn;
    }
    if (bk >= 0) pos = atomicAdd(&h[bk], 1);
    __syncthreads();
    if (tid < 12 && h[tid] > 0) {
        basev[tid] = (tid < 9) ? atomicAdd(&g_ecnt[tid], h[tid])
                               : atomicAdd(&g_ncnt[tid-9], h[tid]);
    }
    __syncthreads();
    if (bk >= 0) {
        int base = basev[bk];
        if (bk < 9) g_ebucket[bk*NETASK + base + pos] = val;
        else        g_nbucket[(bk-9)*NNODE + base + pos] = val;
    }
}

// ---------------- 32x64 @ 64x64 layer via f32x2 ----------------
// Warp tiling: warp = (colHalf, rowGrp); thread = rows {r0, r0+4} x cols [colb, colb+4)
// Per-d weight read per warp = 8 distinct 16B = 128B = 1 smem phase.
static __device__ __forceinline__ void layer64(const float* __restrict__ sIn,
                                               const float* __restrict__ sW,
                                               const float* __restrict__ sb,
                                               int r0, int colb, u64 acc[4]) {
    ulonglong2 bv = *(const ulonglong2*)(sb + colb);
    acc[0] = bv.x; acc[1] = bv.y; acc[2] = bv.x; acc[3] = bv.y;
    const float* in0 = sIn + r0*68;
    const float* in1 = sIn + (r0+4)*68;
    #pragma unroll
    for (int d0 = 0; d0 < 64; d0 += 4) {
        float4 x0 = *(const float4*)(in0 + d0);
        float4 x1 = *(const float4*)(in1 + d0);
        {
            ulonglong2 w = *(const ulonglong2*)(sW + (d0+0)*64 + colb);
            u64 a0 = pack2(x0.x, x0.x), a1 = pack2(x1.x, x1.x);
            ffma2(acc[0], a0, w.x); ffma2(acc[1], a0, w.y);
            ffma2(acc[2], a1, w.x); ffma2(acc[3], a1, w.y);
        }
        {
            ulonglong2 w = *(const ulonglong2*)(sW + (d0+1)*64 + colb);
            u64 a0 = pack2(x0.y, x0.y), a1 = pack2(x1.y, x1.y);
            ffma2(acc[0], a0, w.x); ffma2(acc[1], a0, w.y);
            ffma2(acc[2], a1, w.x); ffma2(acc[3], a1, w.y);
        }
        {
            ulonglong2 w = *(const ulonglong2*)(sW + (d0+2)*64 + colb);
            u64 a0 = pack2(x0.z, x0.z), a1 = pack2(x1.z, x1.z);
            ffma2(acc[0], a0, w.x); ffma2(acc[1], a0, w.y);
            ffma2(acc[2], a1, w.x); ffma2(acc[3], a1, w.y);
        }
        {
            ulonglong2 w = *(const ulonglong2*)(sW + (d0+3)*64 + colb);
            u64 a0 = pack2(x0.w, x0.w), a1 = pack2(x1.w, x1.w);
            ffma2(acc[0], a0, w.x); ffma2(acc[1], a0, w.y);
            ffma2(acc[2], a1, w.x); ffma2(acc[3], a1, w.y);
        }
    }
}

static __device__ __forceinline__ void store_relu(float* __restrict__ sOut,
                                                  int r0, int colb, const u64 acc[4]) {
    float a, b, c, d;
    unpack2(acc[0], a, b); unpack2(acc[1], c, d);
    *(float4*)(sOut + r0*68 + colb) =
        make_float4(fmaxf(a,0.f), fmaxf(b,0.f), fmaxf(c,0.f), fmaxf(d,0.f));
    unpack2(acc[2], a, b); unpack2(acc[3], c, d);
    *(float4*)(sOut + (r0+4)*68 + colb) =
        make_float4(fmaxf(a,0.f), fmaxf(b,0.f), fmaxf(c,0.f), fmaxf(d,0.f));
}

// ---------------- combined node+edge MLP kernel ----------------
__global__ __launch_bounds__(256) void mlp_kernel(
    const float* __restrict__ node_enc, const float* __restrict__ edge_enc,
    const int* __restrict__ cni,
    const float* __restrict__ nW0, const float* __restrict__ nb0,
    const float* __restrict__ nW1, const float* __restrict__ nb1,
    const float* __restrict__ nW2, const float* __restrict__ nb2,
    const float* __restrict__ eW0, const float* __restrict__ eb0,
    const float* __restrict__ eW1, const float* __restrict__ eb1,
    const float* __restrict__ eW2, const float* __restrict__ eb2)
{
    // ---- role mapping (uniform across threads) ----
    int bid = blockIdx.x;
    int g = -1, chunk = 0, acc = 0, cnt = 0;
    bool isEdge = true;
    #pragma unroll
    for (int t = 0; t < NET; t++) {
        int n = g_ecnt[t];
        int c = (n + 31) >> 5;
        if (g < 0 && bid < acc + c) { g = t; chunk = bid - acc; cnt = n; }
        acc += c;
    }
    if (g < 0) {
        isEdge = false;
        int nb = bid - acc; acc = 0;
        #pragma unroll
        for (int t = 0; t < NT; t++) {
            int n = g_ncnt[t];
            int c = (n + 31) >> 5;
            if (g < 0 && nb < acc + c) { g = t; chunk = nb - acc; cnt = n; }
            acc += c;
        }
        if (g < 0) return;
    }
    int base  = chunk * 32;
    int ntask = min(32, cnt - base);

    __shared__ __align__(16) float sW[64*64];
    __shared__ __align__(16) float sb0[64], sb1[64], sb2[64];
    __shared__ __align__(16) float sA[32*68];
    __shared__ __align__(16) float sB[32*68];
    __shared__ int s_idx[32];
    __shared__ int s_off[32];

    int tid  = threadIdx.x;
    int warp = tid >> 5, lane = tid & 31;
    int colb = (warp & 1) * 32 + (lane & 7) * 4;   // 4-col slab
    int r0   = (warp >> 1) * 8 + (lane >> 3);      // rows r0, r0+4

    const float *W0, *W1, *b0, *b1, *inBase;
    if (isEdge) {
        W0 = eW0 + g*4096; W1 = eW1 + g*4096;
        b0 = eb0 + g*64;   b1 = eb1 + g*64;
        inBase = edge_enc;
        if (tid < ntask) {
            int tt = g_ebucket[g*NETASK + base + tid];
            s_idx[tid] = tt;
            int b   = tt / (NC*3);
            int rem = tt - b*(NC*3);
            int c   = rem / 3;
            int p   = rem - 3*c;
            int a0  = (p == 2) ? 1 : 0;
            int a1  = (p == 0) ? 1 : 2;
            int i = clampi(cni[(b*NC + c)*3 + a0], 0, NA-1);
            int j = clampi(cni[(b*NC + c)*3 + a1], 0, NA-1);
            s_off[tid] = ((b*NA + i)*NA + j) * 64;
        }
    } else {
        W0 = nW0 + g*4096; W1 = nW1 + g*4096;
        b0 = nb0 + g*64;   b1 = nb1 + g*64;
        inBase = node_enc;
        if (tid < ntask) {
            int nn = g_nbucket[g*NNODE + base + tid];
            s_idx[tid] = nn;
            s_off[tid] = nn * 64;
        }
    }

    // stage W0 + biases b0,b1
    {
        const float4* w = (const float4*)W0;
        float4* sw = (float4*)sW;
        #pragma unroll
        for (int k = 0; k < 4; k++) sw[tid + 256*k] = w[tid + 256*k];
        if (tid < 64) { sb0[tid] = b0[tid]; sb1[tid] = b1[tid]; }
    }
    __syncthreads();

    // gather input rows (uses s_off), prefetch W1 into registers meanwhile
    float4 pw[4];
    {
        const float4* w = (const float4*)W1;
        #pragma unroll
        for (int k = 0; k < 4; k++) pw[k] = w[tid + 256*k];
    }
    for (int k = tid; k < ntask*16; k += 256) {
        int s = k >> 4, q = k & 15;
        float4 v = *(const float4*)(inBase + (size_t)s_off[s] + q*4);
        *(float4*)(sA + s*68 + q*4) = v;
    }
    __syncthreads();

    u64 a4[4];
    // ---- layer 0: sA -> sB (relu) ----
    layer64(sA, sW, sb0, r0, colb, a4);
    __syncthreads();                    // all reads of sW(W0) done
    store_relu(sB, r0, colb, a4);
    {   // W1 regs -> smem
        float4* sw = (float4*)sW;
        #pragma unroll
        for (int k = 0; k < 4; k++) sw[tid + 256*k] = pw[k];
    }
    // prefetch layer-2 weights
    if (isEdge) {
        const float4* w = (const float4*)(eW2 + g*4096);
        #pragma unroll
        for (int k = 0; k < 4; k++) pw[k] = w[tid + 256*k];
        if (tid < 64) sb2[tid] = eb2[g*64 + tid];
    } else {
        if (tid < 128) pw[0] = ((const float4*)(nW2 + g*512))[tid];
        if (tid < 8)   sb2[tid] = nb2[g*8 + tid];
    }
    __syncthreads();

    // ---- layer 1: sB -> sA (relu) ----
    layer64(sB, sW, sb1, r0, colb, a4);
    __syncthreads();
    store_relu(sA, r0, colb, a4);
    {   // W2 regs -> smem
        float4* sw = (float4*)sW;
        if (isEdge) {
            #pragma unroll
            for (int k = 0; k < 4; k++) sw[tid + 256*k] = pw[k];
        } else {
            if (tid < 128) sw[tid] = pw[0];
        }
    }
    __syncthreads();

    // ---- layer 2 ----
    if (isEdge) {
        layer64(sA, sW, sb2, r0, colb, a4);     // no relu
        float a, b, c, d;
        if (r0 < ntask) {
            unpack2(a4[0], a, b); unpack2(a4[1], c, d);
            *(float4*)(g_ef + (size_t)s_idx[r0]*64 + colb) = make_float4(a, b, c, d);
        }
        if (r0 + 4 < ntask) {
            unpack2(a4[2], a, b); unpack2(a4[3], c, d);
            *(float4*)(g_ef + (size_t)s_idx[r0+4]*64 + colb) = make_float4(a, b, c, d);
        }
    } else {
        // 64 -> 8, one output per thread (32 rows x 8 cols)
        int row = tid >> 3, col = tid & 7;
        float a = sb2[col];
        const float* in = sA + row*68;
        #pragma unroll 16
        for (int d = 0; d < 64; d++) a += in[d] * sW[d*8 + col];
        if (row < ntask) g_nf[(size_t)s_idx[row]*8 + col] = a;
    }
}

// ---------------- kernel: assemble logpi (+ z tail, + counter re-zero) ----
// grid: BS*NC/4 blocks x 256 threads; 4 cliques per block
__global__ __launch_bounds__(256) void assemble_kernel(
    const int* __restrict__ cni, float* __restrict__ out, int writeZ)
{
    int tid = threadIdx.x;
    int sub = tid >> 6;                  // clique within block
    int t   = tid & 63;
    int cq  = blockIdx.x * 4 + sub;      // b*NC + c

    __shared__ float e[4][192];
    __shared__ float nf[4][3][8];

    size_t tbase = (size_t)cq * 192;
    e[sub][t]       = g_ef[tbase + t];
    e[sub][t + 64]  = g_ef[tbase + t + 64];
    e[sub][t + 128] = g_ef[tbase + t + 128];
    if (t < 24) {
        int k = t >> 3, zz = t & 7;
        int b = cq / NC;
        int node = clampi(cni[cq*3 + k], 0, NA-1);
        nf[sub][k][zz] = g_nf[((size_t)b*NA + node)*8 + zz];
    }

    if (blockIdx.x == 0) {               // housekeeping for next replay + z
        if (tid < NET) g_ecnt[tid] = 0;
        if (tid < NT)  g_ncnt[tid] = 0;
        if (writeZ) {
            for (int m = tid; m < 512; m += 256) {
                int i = m >> 6, j = (m >> 3) & 7, k = m & 7;
                float* p = out + OUT_LOGPI + (size_t)m*3;
                p[0] = (float)i; p[1] = (float)j; p[2] = (float)k;
            }
        }
    }
    __syncthreads();

    int z0 = t >> 3, z1 = t & 7;
    float bse = nf[sub][0][z0] + nf[sub][1][z1] + e[sub][z0*8 + z1];
    float r[8];
    #pragma unroll
    for (int z2 = 0; z2 < 8; z2++)
        r[z2] = bse + nf[sub][2][z2] + e[sub][64 + z0*8 + z2] + e[sub][128 + z1*8 + z2];
    float* op = out + (size_t)cq*512 + t*8;
    *(float4*)op       = make_float4(r[0], r[1], r[2], r[3]);
    *(float4*)(op + 4) = make_float4(r[4], r[5], r[6], r[7]);
}

// ---------------- launch ----------------
extern "C" void kernel_launch(void* const* d_in, const int* in_sizes, int n_in,
                              void* d_out, int out_size) {
    const int*   types    = (const int*)d_in[0];
    const float* node_enc = (const float*)d_in[1];
    const float* edge_enc = (const float*)d_in[2];
    const int*   cni      = (const int*)d_in[4];
    const float* nW0 = (const float*)d_in[6];
    const float* nb0 = (const float*)d_in[7];
    const float* nW1 = (const float*)d_in[8];
    const float* nb1 = (const float*)d_in[9];
    const float* nW2 = (const float*)d_in[10];
    const float* nb2 = (const float*)d_in[11];
    const float* eW0 = (const float*)d_in[12];
    const float* eb0 = (const float*)d_in[13];
    const float* eW1 = (const float*)d_in[14];
    const float* eb1 = (const float*)d_in[15];
    const float* eW2 = (const float*)d_in[16];
    const float* eb2 = (const float*)d_in[17];
    float* out = (float*)d_out;

    int writeZ = (out_size >= OUT_LOGPI + 512*3) ? 1 : 0;

    bin_tasks_kernel<<<(NETASK + NNODE) / 256, 256>>>(types, cni);
    mlp_kernel<<<240, 256>>>(node_enc, edge_enc, cni,
                             nW0, nb0, nW1, nb1, nW2, nb2,
                             eW0, eb0, eW1, eb1, eW2, eb2);
    assemble_kernel<<<BS * NC / 4, 256>>>(cni, out, writeZ);
}